// round 1
// baseline (speedup 1.0000x reference)
#include <cuda_runtime.h>

#define NT   24000     // 8 * 3000 tokens
#define DIMD 80
#define HID  320
#define NE   8
#define NL   4
#define TILE_T 64

// ---------------- device scratch (no allocs allowed) ----------------
__device__ float g_buf[2][NT * DIMD];   // ping-pong layer activations
__device__ int   g_cnt[NE];             // per-expert assignment counts
__device__ int   g_tok[NE * NT];        // per-expert token lists
__device__ float g_wt [NE * NT];        // per-expert combine weights (raw logits)

// ---------------- zero next-output buffer + counters ----------------
__global__ void zero_kernel(float* __restrict__ out) {
    int i = blockIdx.x * blockDim.x + threadIdx.x;
    if (i < NT * DIMD) out[i] = 0.f;
    if (blockIdx.x == 0 && threadIdx.x < NE) g_cnt[threadIdx.x] = 0;
}

// ---------------- router: logits + stable top-2 + bucketize ----------------
__global__ __launch_bounds__(256) void router_kernel(
    const float* __restrict__ x, const float* __restrict__ Wg,
    const float* __restrict__ bg)
{
    __shared__ float wgs[DIMD * NE];
    __shared__ float bgs[NE];
    __shared__ int s_cnt[NE];
    __shared__ int s_base[NE];

    int tid = threadIdx.x;
    for (int i = tid; i < DIMD * NE; i += 256) wgs[i] = Wg[i];
    if (tid < NE) { bgs[tid] = bg[tid]; s_cnt[tid] = 0; }
    __syncthreads();

    int t = blockIdx.x * 256 + tid;
    int e0 = 0, e1 = 0, p0 = 0, p1 = 0;
    float v0 = 0.f, v1 = 0.f;
    bool valid = (t < NT);

    if (valid) {
        float lg[NE];
#pragma unroll
        for (int e = 0; e < NE; e++) lg[e] = bgs[e];
        const float4* xr = reinterpret_cast<const float4*>(x + (long)t * DIMD);
#pragma unroll
        for (int dq = 0; dq < DIMD / 4; dq++) {
            float4 xv = xr[dq];
#pragma unroll
            for (int e = 0; e < NE; e++) {
                lg[e] = fmaf(xv.x, wgs[(dq * 4 + 0) * NE + e], lg[e]);
                lg[e] = fmaf(xv.y, wgs[(dq * 4 + 1) * NE + e], lg[e]);
                lg[e] = fmaf(xv.z, wgs[(dq * 4 + 2) * NE + e], lg[e]);
                lg[e] = fmaf(xv.w, wgs[(dq * 4 + 3) * NE + e], lg[e]);
            }
        }
        // stable top-2 (strict '>' keeps earlier index on ties, matching lax.top_k)
        float m0 = lg[0]; int i0 = 0;
        float m1 = -3.402823466e38f; int i1 = 0;
#pragma unroll
        for (int e = 1; e < NE; e++) {
            float v = lg[e];
            if (v > m0)      { m1 = m0; i1 = i0; m0 = v; i0 = e; }
            else if (v > m1) { m1 = v;  i1 = e; }
        }
        e0 = i0; v0 = m0; e1 = i1; v1 = m1;
        p0 = atomicAdd(&s_cnt[e0], 1);
        p1 = atomicAdd(&s_cnt[e1], 1);
    }
    __syncthreads();
    if (tid < NE) s_base[tid] = atomicAdd(&g_cnt[tid], s_cnt[tid]);
    __syncthreads();
    if (valid) {
        int q0 = s_base[e0] + p0;
        g_tok[e0 * NT + q0] = t;  g_wt[e0 * NT + q0] = v0;
        int q1 = s_base[e1] + p1;
        g_tok[e1 * NT + q1] = t;  g_wt[e1 * NT + q1] = v1;
    }
}

// ---------------- fused expert FFN: relu(X@W1+b1)@W2+b2, weighted scatter ----------------
// smem layout (floats): Ws[25600] | Hs[64*324] | Xs[80*65] | b1s[320] | b2s[80] | swt[64] | stok[64]
#define XS_STRIDE 65
#define HS_STRIDE 324
#define SMEM_FLOATS (25600 + TILE_T * HS_STRIDE + DIMD * XS_STRIDE + HID + DIMD + TILE_T + TILE_T)
#define SMEM_BYTES (SMEM_FLOATS * 4)

__global__ __launch_bounds__(256, 1) void ffn_kernel(
    const float* __restrict__ xin, float* __restrict__ out,
    const float* __restrict__ W1, const float* __restrict__ b1,
    const float* __restrict__ W2, const float* __restrict__ b2)
{
    extern __shared__ float sm[];
    float* Ws   = sm;
    float* Hs   = sm + 25600;
    float* Xs   = Hs + TILE_T * HS_STRIDE;
    float* b1s  = Xs + DIMD * XS_STRIDE;
    float* b2s  = b1s + HID;
    float* swt  = b2s + DIMD;
    int*   stok = (int*)(swt + TILE_T);

    int e = blockIdx.y;
    int cnt = g_cnt[e];
    int start = blockIdx.x * TILE_T;
    if (start >= cnt) return;
    int tid = threadIdx.x;

    if (tid < TILE_T) {
        int slot = start + tid;
        if (slot < cnt) { stok[tid] = g_tok[e * NT + slot]; swt[tid] = g_wt[e * NT + slot]; }
        else            { stok[tid] = -1;                   swt[tid] = 0.f; }
    }
    for (int i = tid; i < HID; i += 256) b1s[i] = b1[e * HID + i];
    if (tid < DIMD) b2s[tid] = b2[e * DIMD + tid];
    __syncthreads();

    // gather X tile (transposed: Xs[d][t], padded stride)
    for (int i = tid; i < TILE_T * DIMD; i += 256) {
        int tt = i / DIMD, d = i % DIMD;
        int tok = stok[tt];
        Xs[d * XS_STRIDE + tt] = (tok >= 0) ? xin[(long)tok * DIMD + d] : 0.f;
    }
    // stage W1 [80][320]
    const float* w1p = W1 + (long)e * DIMD * HID;
    for (int i = tid; i < DIMD * HID; i += 256) Ws[i] = w1p[i];
    __syncthreads();

    int tx = tid & 15, ty = tid >> 4;
    int h0 = tx * 20, t0 = ty * 4;

    // ---- GEMM1: H[64x320] = relu(X[64x80] @ W1[80x320] + b1) ----
    float acc[4][20];
#pragma unroll
    for (int k = 0; k < 4; k++)
#pragma unroll
        for (int j = 0; j < 20; j++) acc[k][j] = 0.f;

    for (int d = 0; d < DIMD; ++d) {
        float xv[4];
#pragma unroll
        for (int k = 0; k < 4; k++) xv[k] = Xs[d * XS_STRIDE + t0 + k];
        float w[20];
        const float4* wr = reinterpret_cast<const float4*>(Ws + d * HID + h0);
#pragma unroll
        for (int q = 0; q < 5; q++) reinterpret_cast<float4*>(w)[q] = wr[q];
#pragma unroll
        for (int j = 0; j < 20; j++) {
#pragma unroll
            for (int k = 0; k < 4; k++) acc[k][j] = fmaf(xv[k], w[j], acc[k][j]);
        }
    }
    // bias + relu -> Hs (float4 stores, padded stride kills bank conflicts on GEMM2 reads)
#pragma unroll
    for (int k = 0; k < 4; k++) {
#pragma unroll
        for (int q = 0; q < 5; q++) {
            float4 v;
            v.x = fmaxf(acc[k][q * 4 + 0] + b1s[h0 + q * 4 + 0], 0.f);
            v.y = fmaxf(acc[k][q * 4 + 1] + b1s[h0 + q * 4 + 1], 0.f);
            v.z = fmaxf(acc[k][q * 4 + 2] + b1s[h0 + q * 4 + 2], 0.f);
            v.w = fmaxf(acc[k][q * 4 + 3] + b1s[h0 + q * 4 + 3], 0.f);
            *reinterpret_cast<float4*>(Hs + (t0 + k) * HS_STRIDE + h0 + q * 4) = v;
        }
    }
    __syncthreads();

    // stage W2 [320][80] into the same smem slot
    const float* w2p = W2 + (long)e * HID * DIMD;
    for (int i = tid; i < HID * DIMD; i += 256) Ws[i] = w2p[i];
    __syncthreads();

    // ---- GEMM2: Y[64x80] = H[64x320] @ W2[320x80] + b2, scale by wt, scatter ----
    int dd0 = tx * 5;
    float acc2[4][5];
#pragma unroll
    for (int k = 0; k < 4; k++)
#pragma unroll
        for (int j = 0; j < 5; j++) acc2[k][j] = 0.f;

    for (int h = 0; h < HID; ++h) {
        float hv[4];
#pragma unroll
        for (int k = 0; k < 4; k++) hv[k] = Hs[(t0 + k) * HS_STRIDE + h];
        const float* w2r = Ws + h * DIMD + dd0;
#pragma unroll
        for (int j = 0; j < 5; j++) {
            float w = w2r[j];
#pragma unroll
            for (int k = 0; k < 4; k++) acc2[k][j] = fmaf(hv[k], w, acc2[k][j]);
        }
    }
#pragma unroll
    for (int k = 0; k < 4; k++) {
        int tok = stok[t0 + k];
        if (tok < 0) continue;
        float wt = swt[t0 + k];
#pragma unroll
        for (int j = 0; j < 5; j++) {
            atomicAdd(out + (long)tok * DIMD + dd0 + j,
                      wt * (acc2[k][j] + b2s[dd0 + j]));
        }
    }
}

// ---------------- launch ----------------
extern "C" void kernel_launch(void* const* d_in, const int* in_sizes, int n_in,
                              void* d_out, int out_size) {
    const float* x  = (const float*)d_in[0];
    const float* Wg = (const float*)d_in[1];
    const float* bg = (const float*)d_in[2];
    const float* W1 = (const float*)d_in[3];
    const float* b1 = (const float*)d_in[4];
    const float* W2 = (const float*)d_in[5];
    const float* b2 = (const float*)d_in[6];
    float* out = (float*)d_out;

    cudaFuncSetAttribute(ffn_kernel, cudaFuncAttributeMaxDynamicSharedMemorySize, SMEM_BYTES);

    float* buf0 = nullptr;
    cudaGetSymbolAddress((void**)&buf0, g_buf);
    float* buf1 = buf0 + NT * DIMD;

    const float* cur = x;
    for (int l = 0; l < NL; ++l) {
        float* nxt = (l == NL - 1) ? out : ((l & 1) ? buf1 : buf0);

        zero_kernel<<<(NT * DIMD + 255) / 256, 256>>>(nxt);
        router_kernel<<<(NT + 255) / 256, 256>>>(cur, Wg + l * DIMD * NE, bg + l * NE);

        dim3 grid((NT + TILE_T - 1) / TILE_T, NE);
        ffn_kernel<<<grid, 256, SMEM_BYTES>>>(cur, nxt, W1, b1, W2, b2);

        cur = nxt;
    }
}